// round 13
// baseline (speedup 1.0000x reference)
#include <cuda_runtime.h>
#include <cuda_bf16.h>
#include <cstdint>

// Problem constants
constexpr int B_  = 4;
constexpr int S_  = 2048;
constexpr int D_  = 1024;
constexpr int NR  = B_ * S_;

// ---------------------------------------------------------------------------
// Persistent bf16 hi/lo operand arrays + fp32 scores (device globals)
// ---------------------------------------------------------------------------
__device__ __nv_bfloat16 g_Xh [NR * D_];
__device__ __nv_bfloat16 g_Xl [NR * D_];
__device__ __nv_bfloat16 g_Wth[3 * D_ * D_];     // W^T, [z][e][d]
__device__ __nv_bfloat16 g_Wtl[3 * D_ * D_];
__device__ __nv_bfloat16 g_Qh [NR * D_];
__device__ __nv_bfloat16 g_Ql [NR * D_];
__device__ __nv_bfloat16 g_Kh [NR * D_];
__device__ __nv_bfloat16 g_Kl [NR * D_];
__device__ __nv_bfloat16 g_Vh [NR * D_];         // row-major [b*s][d]
__device__ __nv_bfloat16 g_Vl [NR * D_];
__device__ __nv_bfloat16 g_Vth[NR * D_];         // V^T, [b][d][s]
__device__ __nv_bfloat16 g_Vtl[NR * D_];
__device__ float         g_SC [(size_t)B_ * S_ * S_];
__device__ __nv_bfloat16 g_Ph [(size_t)B_ * S_ * S_];
__device__ __nv_bfloat16 g_Pl [(size_t)B_ * S_ * S_];

// ---------------------------------------------------------------------------
// Helpers
// ---------------------------------------------------------------------------
__device__ __forceinline__ uint32_t swz64(uint32_t off) {   // SW64: 64B rows
    return off ^ ((off >> 3) & 0x30);
}
__device__ __forceinline__ uint32_t smem_u32(const void* p) {
    uint32_t a;
    asm("{ .reg .u64 t; cvta.to.shared.u64 t, %1; cvt.u32.u64 %0, t; }" : "=r"(a) : "l"(p));
    return a;
}
__device__ __forceinline__ void split2(float v, __nv_bfloat16& h, __nv_bfloat16& l) {
    h = __float2bfloat16(v);
    l = __float2bfloat16(v - __bfloat162float(h));
}

#define LDSM_X4(r0, r1, r2, r3, addr) \
    asm volatile("ldmatrix.sync.aligned.m8n8.x4.shared.b16 {%0,%1,%2,%3}, [%4];" \
        : "=r"(r0), "=r"(r1), "=r"(r2), "=r"(r3) : "r"(addr))

#define MMA_BF16(c, a, b0, b1) \
    asm volatile("mma.sync.aligned.m16n8k16.row.col.f32.bf16.bf16.f32 " \
        "{%0,%1,%2,%3}, {%4,%5,%6,%7}, {%8,%9}, {%0,%1,%2,%3};" \
        : "+f"((c)[0]), "+f"((c)[1]), "+f"((c)[2]), "+f"((c)[3]) \
        : "r"((a)[0]), "r"((a)[1]), "r"((a)[2]), "r"((a)[3]), "r"(b0), "r"(b1))

__device__ __forceinline__ void cp16(uint32_t dst, const void* src) {
    asm volatile("cp.async.cg.shared.global [%0], [%1], 16;" :: "r"(dst), "l"(src));
}
#define CP_COMMIT() asm volatile("cp.async.commit_group;" ::: "memory")
#define CP_WAIT(n)  asm volatile("cp.async.wait_group %0;" :: "n"(n) : "memory")

// ---------------------------------------------------------------------------
// Conversion kernels (run once, memory-bound)
// ---------------------------------------------------------------------------
__global__ void __launch_bounds__(256) ca_split_x(const float* __restrict__ X)
{
    int idx = (blockIdx.x * 256 + threadIdx.x) * 4;
    if (idx >= NR * D_) return;
    float4 f = *(const float4*)(X + idx);
    __nv_bfloat16 h[4], l[4];
    split2(f.x, h[0], l[0]); split2(f.y, h[1], l[1]);
    split2(f.z, h[2], l[2]); split2(f.w, h[3], l[3]);
    *(uint2*)(g_Xh + idx) = *(uint2*)h;
    *(uint2*)(g_Xl + idx) = *(uint2*)l;
}

// W [d][e] fp32 -> W^T [e][d] bf16 hi/lo, 32x32 smem tiles
__global__ void __launch_bounds__(256) ca_tsplit_w(
    const float* __restrict__ Wq, const float* __restrict__ Wk,
    const float* __restrict__ Wv)
{
    __shared__ float tf[32][33];
    const int z = blockIdx.z;
    const float* W = (z == 0) ? Wq : (z == 1) ? Wk : Wv;
    const int dt = blockIdx.y * 32, et = blockIdx.x * 32;
    const int tx = threadIdx.x & 31, ty = threadIdx.x >> 5;   // ty 0..7
    #pragma unroll
    for (int i = 0; i < 32; i += 8)
        tf[ty + i][tx] = W[(size_t)(dt + ty + i) * D_ + et + tx];
    __syncthreads();
    __nv_bfloat16* Oh = g_Wth + (size_t)z * D_ * D_;
    __nv_bfloat16* Ol = g_Wtl + (size_t)z * D_ * D_;
    #pragma unroll
    for (int i = 0; i < 32; i += 8) {
        float v = tf[tx][ty + i];
        __nv_bfloat16 h, l; split2(v, h, l);
        Oh[(size_t)(et + ty + i) * D_ + dt + tx] = h;
        Ol[(size_t)(et + ty + i) * D_ + dt + tx] = l;
    }
}

// bf16 transpose: V [b][s][d] -> V^T [b][d][s] (hi and lo)
__global__ void __launch_bounds__(256) ca_transpose_v()
{
    __shared__ __nv_bfloat16 th[32][33], tl[32][33];
    const int dt = blockIdx.x * 32, st = blockIdx.y * 32, b = blockIdx.z;
    const int tx = threadIdx.x & 31, ty = threadIdx.x >> 5;
    const __nv_bfloat16* Sh = g_Vh + (size_t)b * S_ * D_;
    const __nv_bfloat16* Sl = g_Vl + (size_t)b * S_ * D_;
    #pragma unroll
    for (int i = 0; i < 32; i += 8) {
        th[ty + i][tx] = Sh[(size_t)(st + ty + i) * D_ + dt + tx];
        tl[ty + i][tx] = Sl[(size_t)(st + ty + i) * D_ + dt + tx];
    }
    __syncthreads();
    __nv_bfloat16* Oh = g_Vth + (size_t)b * D_ * S_;
    __nv_bfloat16* Ol = g_Vtl + (size_t)b * D_ * S_;
    #pragma unroll
    for (int i = 0; i < 32; i += 8) {
        Oh[(size_t)(dt + ty + i) * S_ + st + tx] = th[tx][ty + i];
        Ol[(size_t)(dt + ty + i) * S_ + st + tx] = tl[tx][ty + i];
    }
}

// ---------------------------------------------------------------------------
// GEMM kernel: 128x128 tile, K-chunk 32 (SW64 tiles), 3-stage cp.async
// pipeline, split-bf16 3-pass mma.sync. 96KB smem -> 2 CTAs/SM.
// 8 warps, 4(m) x 2(n) warp grid.
// MODE 0: Q/K/V proj (bf16 hi/lo out)
// MODE 1: scores (fp32*scale out, triangular 1D grid)
// MODE 2: PV (fp32 out, causal K bound, heavy-first qT order)
// ---------------------------------------------------------------------------
constexpr int CH_K    = 32;             // K elements per chunk
constexpr int TILE_B  = 8192;           // 128 rows x 64B
constexpr int STAGE_B = 4 * TILE_B;     // Ah, Al, Bh, Bl = 32KB
constexpr int NSTAGE  = 3;
constexpr int SMEM_TOTAL = NSTAGE * STAGE_B;   // 98304

__device__ __forceinline__ void load_tile(const __nv_bfloat16* __restrict__ src,
                                          int ld, uint32_t dstbase, int tid) {
    #pragma unroll
    for (int it = 0; it < 2; it++) {
        int idx = it * 256 + tid;                  // 0..511
        int r = idx >> 2, cb = (idx & 3) * 16;     // cb in bytes, row is 64B
        cp16(dstbase + swz64((uint32_t)r * 64u + cb),
             src + (size_t)r * ld + (cb >> 1));
    }
}

template<int MODE>
__global__ void __launch_bounds__(256, 2) ca_mma_kernel(float* __restrict__ Out)
{
    extern __shared__ char smem[];

    const __nv_bfloat16 *AhP, *AlP, *BhP, *BlP;
    int lda, ldb, nchunks;
    float* Cf = nullptr; int ldc = D_; float scale = 1.0f;
    __nv_bfloat16 *Ch = nullptr, *Cl = nullptr;

    if constexpr (MODE == 0) {
        int nT = blockIdx.x, mT = blockIdx.y, z = blockIdx.z;
        AhP = g_Xh + (size_t)mT * 128 * D_;
        AlP = g_Xl + (size_t)mT * 128 * D_;                       lda = D_;
        BhP = g_Wth + (size_t)z * D_ * D_ + (size_t)nT * 128 * D_;
        BlP = g_Wtl + (size_t)z * D_ * D_ + (size_t)nT * 128 * D_; ldb = D_;
        size_t co = (size_t)mT * 128 * D_ + nT * 128;
        Ch = ((z == 0) ? g_Qh : (z == 1) ? g_Kh : g_Vh) + co;
        Cl = ((z == 0) ? g_Ql : (z == 1) ? g_Kl : g_Vl) + co;
        ldc = D_; nchunks = D_ / CH_K;
    } else if constexpr (MODE == 1) {
        // triangular decode: flat index -> (qt, kt), kt <= qt
        int i = blockIdx.x, b = blockIdx.z;
        int qt = (int)((sqrtf(8.f * (float)i + 1.f) - 1.f) * 0.5f);
        while ((qt + 1) * (qt + 2) / 2 <= i) qt++;
        while (qt * (qt + 1) / 2 > i) qt--;
        int kt = i - qt * (qt + 1) / 2;
        AhP = g_Qh + (size_t)b * S_ * D_ + (size_t)qt * 128 * D_;
        AlP = g_Ql + (size_t)b * S_ * D_ + (size_t)qt * 128 * D_;  lda = D_;
        BhP = g_Kh + (size_t)b * S_ * D_ + (size_t)kt * 128 * D_;
        BlP = g_Kl + (size_t)b * S_ * D_ + (size_t)kt * 128 * D_;  ldb = D_;
        Cf = g_SC + (size_t)b * S_ * S_ + (size_t)qt * 128 * S_ + kt * 128;
        ldc = S_; nchunks = D_ / CH_K; scale = 0.03125f;
    } else {
        int nT = blockIdx.x, b = blockIdx.z;
        int qT = gridDim.y - 1 - blockIdx.y;    // heavy blocks first
        AhP = g_Ph + (size_t)b * S_ * S_ + (size_t)qT * 128 * S_;
        AlP = g_Pl + (size_t)b * S_ * S_ + (size_t)qT * 128 * S_;  lda = S_;
        BhP = g_Vth + (size_t)b * D_ * S_ + (size_t)nT * 128 * S_;
        BlP = g_Vtl + (size_t)b * D_ * S_ + (size_t)nT * 128 * S_; ldb = S_;
        Cf = Out + (size_t)b * S_ * D_ + (size_t)qT * 128 * D_ + nT * 128;
        ldc = D_; nchunks = (qT + 1) * (128 / CH_K);   // causal K bound
    }

    const uint32_t sb = smem_u32(smem);
    const int tid  = threadIdx.x;
    const int wid  = tid >> 5, lane = tid & 31;
    const int wm   = wid >> 1, wn = wid & 1;
    const int lrow  = lane & 15;
    const int lkofs = (lane >> 4) * 8;

    float acc[2][8][4] = {};

    // prologue: fill 2 stages
    {
        uint32_t base = sb;
        load_tile(AhP, lda, base,              tid);
        load_tile(AlP, lda, base + TILE_B,     tid);
        load_tile(BhP, ldb, base + 2 * TILE_B, tid);
        load_tile(BlP, ldb, base + 3 * TILE_B, tid);
        CP_COMMIT();
        if (nchunks > 1) {
            base = sb + STAGE_B;
            load_tile(AhP + CH_K, lda, base,              tid);
            load_tile(AlP + CH_K, lda, base + TILE_B,     tid);
            load_tile(BhP + CH_K, ldb, base + 2 * TILE_B, tid);
            load_tile(BlP + CH_K, ldb, base + 3 * TILE_B, tid);
            CP_COMMIT();
        }
    }

    int st = 0;
    for (int ch = 0; ch < nchunks; ch++) {
        if (ch + 1 < nchunks) { CP_WAIT(1); } else { CP_WAIT(0); }
        __syncthreads();

        if (ch + 2 < nchunks) {
            const int k0 = (ch + 2) * CH_K;
            int st2 = st + 2; if (st2 >= NSTAGE) st2 -= NSTAGE;
            uint32_t base = sb + st2 * STAGE_B;
            load_tile(AhP + k0, lda, base,              tid);
            load_tile(AlP + k0, lda, base + TILE_B,     tid);
            load_tile(BhP + k0, ldb, base + 2 * TILE_B, tid);
            load_tile(BlP + k0, ldb, base + 3 * TILE_B, tid);
            CP_COMMIT();
        }

        const uint32_t sB = sb + st * STAGE_B;
        #pragma unroll
        for (int ks = 0; ks < 2; ks++) {
            const uint32_t colb = (uint32_t)(ks * 16 + lkofs) * 2u;

            uint32_t ah[2][4], al[2][4];
            #pragma unroll
            for (int mt = 0; mt < 2; mt++) {
                uint32_t sw = swz64((uint32_t)(wm * 32 + mt * 16 + lrow) * 64u + colb);
                LDSM_X4(ah[mt][0], ah[mt][1], ah[mt][2], ah[mt][3], sB + sw);
                LDSM_X4(al[mt][0], al[mt][1], al[mt][2], al[mt][3], sB + TILE_B + sw);
            }
            uint32_t bb[4][4];
            #pragma unroll
            for (int nt2 = 0; nt2 < 4; nt2++) {
                uint32_t sw = swz64((uint32_t)(wn * 64 + nt2 * 16 + lrow) * 64u + colb);
                LDSM_X4(bb[nt2][0], bb[nt2][1], bb[nt2][2], bb[nt2][3],
                        sB + 2 * TILE_B + sw);
            }
            #pragma unroll
            for (int mt = 0; mt < 2; mt++)
                #pragma unroll
                for (int nt = 0; nt < 8; nt++) {
                    const int nt2 = nt >> 1, pr = nt & 1;
                    MMA_BF16(acc[mt][nt], ah[mt], bb[nt2][pr], bb[nt2][pr + 2]);
                }
            #pragma unroll
            for (int mt = 0; mt < 2; mt++)
                #pragma unroll
                for (int nt = 0; nt < 8; nt++) {
                    const int nt2 = nt >> 1, pr = nt & 1;
                    MMA_BF16(acc[mt][nt], al[mt], bb[nt2][pr], bb[nt2][pr + 2]);
                }
            #pragma unroll
            for (int nt2 = 0; nt2 < 4; nt2++) {
                uint32_t sw = swz64((uint32_t)(wn * 64 + nt2 * 16 + lrow) * 64u + colb);
                LDSM_X4(bb[nt2][0], bb[nt2][1], bb[nt2][2], bb[nt2][3],
                        sB + 3 * TILE_B + sw);
            }
            #pragma unroll
            for (int mt = 0; mt < 2; mt++)
                #pragma unroll
                for (int nt = 0; nt < 8; nt++) {
                    const int nt2 = nt >> 1, pr = nt & 1;
                    MMA_BF16(acc[mt][nt], ah[mt], bb[nt2][pr], bb[nt2][pr + 2]);
                }
        }
        if (++st == NSTAGE) st = 0;
    }

    // Epilogue
    const int erow = wm * 32 + (lane >> 2);
    const int ecol = wn * 64 + (lane & 3) * 2;
    #pragma unroll
    for (int mt = 0; mt < 2; mt++) {
        #pragma unroll
        for (int nt = 0; nt < 8; nt++) {
            const int r0 = erow + mt * 16, r1 = r0 + 8, c = ecol + nt * 8;
            if constexpr (MODE == 0) {
                __nv_bfloat16 h0, l0, h1, l1;
                split2(acc[mt][nt][0], h0, l0); split2(acc[mt][nt][1], h1, l1);
                *(__nv_bfloat162*)(Ch + (size_t)r0 * ldc + c) = __nv_bfloat162(h0, h1);
                *(__nv_bfloat162*)(Cl + (size_t)r0 * ldc + c) = __nv_bfloat162(l0, l1);
                split2(acc[mt][nt][2], h0, l0); split2(acc[mt][nt][3], h1, l1);
                *(__nv_bfloat162*)(Ch + (size_t)r1 * ldc + c) = __nv_bfloat162(h0, h1);
                *(__nv_bfloat162*)(Cl + (size_t)r1 * ldc + c) = __nv_bfloat162(l0, l1);
            } else {
                *(float2*)(Cf + (size_t)r0 * ldc + c) =
                    make_float2(acc[mt][nt][0] * scale, acc[mt][nt][1] * scale);
                *(float2*)(Cf + (size_t)r1 * ldc + c) =
                    make_float2(acc[mt][nt][2] * scale, acc[mt][nt][3] * scale);
            }
        }
    }
}

// ---------------------------------------------------------------------------
// Causal row softmax: fp32 scores -> bf16 hi/lo probs
// ---------------------------------------------------------------------------
__global__ void __launch_bounds__(256) ca_softmax_kernel()
{
    __shared__ float buf[S_];
    __shared__ float red[256];

    const int row = blockIdx.x;
    const int b   = row >> 11;
    const int q   = row & (S_ - 1);
    const float* sc = g_SC + (size_t)b * S_ * S_ + (size_t)q * S_;
    __nv_bfloat16* ph = g_Ph + (size_t)b * S_ * S_ + (size_t)q * S_;
    __nv_bfloat16* pl = g_Pl + (size_t)b * S_ * S_ + (size_t)q * S_;
    const int len = q + 1;
    const int tid = threadIdx.x;

    float m = -3.4e38f;
    for (int i = tid; i < len; i += 256) {
        float v = sc[i];
        buf[i] = v;
        m = fmaxf(m, v);
    }
    red[tid] = m;
    __syncthreads();
    #pragma unroll
    for (int s = 128; s > 0; s >>= 1) {
        if (tid < s) red[tid] = fmaxf(red[tid], red[tid + s]);
        __syncthreads();
    }
    m = red[0];
    __syncthreads();

    float sum = 0.f;
    for (int i = tid; i < len; i += 256) {
        float e = __expf(buf[i] - m);
        buf[i] = e;
        sum += e;
    }
    red[tid] = sum;
    __syncthreads();
    #pragma unroll
    for (int s = 128; s > 0; s >>= 1) {
        if (tid < s) red[tid] += red[tid + s];
        __syncthreads();
    }
    const float inv = 1.0f / red[0];

    for (int i = tid; i < len; i += 256) {
        __nv_bfloat16 h, l;
        split2(buf[i] * inv, h, l);
        ph[i] = h; pl[i] = l;
    }
    const __nv_bfloat16 z = __float2bfloat16(0.f);
    for (int i = len + tid; i < S_; i += 256) { ph[i] = z; pl[i] = z; }
}

// ---------------------------------------------------------------------------
extern "C" void kernel_launch(void* const* d_in, const int* in_sizes, int n_in,
                              void* d_out, int out_size)
{
    const float* x  = (const float*)d_in[0];
    const float* Wq = (const float*)d_in[1];
    const float* Wk = (const float*)d_in[2];
    const float* Wv = (const float*)d_in[3];
    float* out = (float*)d_out;

    cudaFuncSetAttribute(ca_mma_kernel<0>, cudaFuncAttributeMaxDynamicSharedMemorySize, SMEM_TOTAL);
    cudaFuncSetAttribute(ca_mma_kernel<1>, cudaFuncAttributeMaxDynamicSharedMemorySize, SMEM_TOTAL);
    cudaFuncSetAttribute(ca_mma_kernel<2>, cudaFuncAttributeMaxDynamicSharedMemorySize, SMEM_TOTAL);

    // 0) one-time operand conversion
    ca_split_x<<<(NR * D_ / 4 + 255) / 256, 256>>>(x);
    ca_tsplit_w<<<dim3(D_ / 32, D_ / 32, 3), 256>>>(Wq, Wk, Wv);

    // 1) QKV projections (writes Q/K/V as bf16 hi/lo)
    ca_mma_kernel<0><<<dim3(D_ / 128, NR / 128, 3), 256, SMEM_TOTAL>>>(out);

    // 1b) V -> V^T
    ca_transpose_v<<<dim3(D_ / 32, S_ / 32, B_), 256>>>();

    // 2) Scores: triangular grid, 136 live tiles per batch
    constexpr int NTRI = (S_ / 128) * (S_ / 128 + 1) / 2;   // 136
    ca_mma_kernel<1><<<dim3(NTRI, 1, B_), 256, SMEM_TOTAL>>>(out);

    // 3) Row softmax -> bf16 hi/lo probs
    ca_softmax_kernel<<<NR, 256>>>();

    // 4) O = P @ V (heavy qT first)
    ca_mma_kernel<2><<<dim3(D_ / 128, S_ / 128, B_), 256, SMEM_TOTAL>>>(out);
}